// round 7
// baseline (speedup 1.0000x reference)
#include <cuda_runtime.h>
#include <math.h>

#define Tt 64
#define Bb 256
#define Nn 256
#define Mm 128
#define Hh 1024
#define Ii 128
#define ICt 256
#define EPSf 1e-8f
#define NCTA 256
#define NTHR 256
#define SAS 260   // smem A-tile row stride (floats): 260%32==4 -> bank-spread, %4==0 -> float4 ok

// ---------------- persistent device scratch ----------------
__device__ __align__(16) float g_mem[Bb*Nn*Mm];   // 33.5 MB, L2-resident
__device__ __align__(16) float g_ht [Bb*Hh];
__device__ __align__(16) float g_k  [2*Bb*Mm];
__device__ __align__(16) float g_e  [Bb*Mm];
__device__ __align__(16) float g_a  [Bb*Mm];
__device__ __align__(16) float g_rd [Bb*Mm];
__device__            float g_small[Bb*12];
__device__ unsigned g_barcnt;
__device__ volatile unsigned g_bargen;

// ---------------- grid barrier (all 256 CTAs co-resident) ----------------
__device__ __forceinline__ void gbar(){
    __threadfence();
    __syncthreads();
    if (threadIdx.x == 0){
        unsigned gen = g_bargen;
        if (atomicAdd(&g_barcnt, 1u) == NCTA - 1u){
            g_barcnt = 0u;
            __threadfence();
            g_bargen = gen + 1u;
        } else {
            while (g_bargen == gen) { __nanosleep(64); }
        }
        __threadfence();
    }
    __syncthreads();
}

// ---------------- block reductions over 256 threads ----------------
__device__ __forceinline__ float bredSum(float v, float* s_red){
    int lane = threadIdx.x & 31, wid = threadIdx.x >> 5;
    #pragma unroll
    for (int off = 16; off; off >>= 1) v += __shfl_xor_sync(0xffffffffu, v, off);
    if (lane == 0) s_red[wid] = v;
    __syncthreads();
    if (threadIdx.x == 0){
        float s = 0.f;
        #pragma unroll
        for (int j = 0; j < 8; j++) s += s_red[j];
        s_red[32] = s;
    }
    __syncthreads();
    return s_red[32];
}
__device__ __forceinline__ float bredMax(float v, float* s_red){
    int lane = threadIdx.x & 31, wid = threadIdx.x >> 5;
    #pragma unroll
    for (int off = 16; off; off >>= 1) v = fmaxf(v, __shfl_xor_sync(0xffffffffu, v, off));
    if (lane == 0) s_red[wid] = v;
    __syncthreads();
    if (threadIdx.x == 0){
        float s = -3.4e38f;
        #pragma unroll
        for (int j = 0; j < 8; j++) s = fmaxf(s, s_red[j]);
        s_red[32] = s;
    }
    __syncthreads();
    return s_red[32];
}

__device__ __forceinline__ float softplusf(float x){
    return fmaxf(x, 0.f) + log1pf(expf(-fabsf(x)));
}
__device__ __forceinline__ float sigmoidf_(float x){
    return 1.f / (1.f + expf(-x));
}

// ---------------- the persistent NTM kernel ----------------
__global__ void __launch_bounds__(NTHR, 2) ntm_kernel(
    const float* __restrict__ x,
    const float* __restrict__ Wc,   const float* __restrict__ bc,
    const float* __restrict__ Wk,   const float* __restrict__ bk,
    const float* __restrict__ Wb,   const float* __restrict__ bb,
    const float* __restrict__ Wg,   const float* __restrict__ bg,
    const float* __restrict__ Ws,   const float* __restrict__ bs,
    const float* __restrict__ Wgam, const float* __restrict__ bgam,
    const float* __restrict__ We,   const float* __restrict__ be,
    const float* __restrict__ Wa,   const float* __restrict__ ba,
    const float* __restrict__ Wo,   const float* __restrict__ bo,
    const float* __restrict__ memory0,
    const float* __restrict__ ww0,  const float* __restrict__ rw0,
    const float* __restrict__ read0,
    float* __restrict__ out)
{
    __shared__ __align__(16) float s_buf[32*SAS];   // 33.3 KB: GEMM A-tile, reused as P3/P4 scratch
    __shared__ float s_ww[Nn];
    __shared__ float s_rw[Nn];
    __shared__ float s_red[40];

    const int tid  = threadIdx.x;
    const int cta  = blockIdx.x;
    const int b    = cta;
    const int wid  = tid >> 5, lane = tid & 31;

    // P3/P4 scratch carve (inside s_buf; all offsets float4-safe)
    float*  s_kw  = s_buf;            // 128
    float*  s_kr  = s_buf + 128;      // 128
    float*  s_e   = s_buf + 256;      // 128
    float*  s_a   = s_buf + 384;      // 128
    float*  s_sm  = s_buf + 512;      // 16
    float4* s_prd = (float4*)(s_buf + 1024);  // 256 float4
    float*  s_zw  = s_buf + 2048;     // 256
    float*  s_zr  = s_buf + 2304;     // 256
    float*  s_tmp = s_buf + 2560;     // 256
    float*  s_rdv = s_buf + 2816;     // 128

    // ---------------- init ----------------
    {
        float4*       md = ((float4*)g_mem) + b * (Nn*Mm/4);
        const float4* ms = (const float4*)memory0;
        for (int i = tid; i < Nn*Mm/4; i += NTHR) md[i] = ms[i];
        if (tid < Mm) __stcg(&g_rd[b*Mm + tid], read0[tid]);
        float v  = ww0[tid];
        float mx = bredMax(v, s_red);
        float e  = expf(v - mx);
        float s  = bredSum(e, s_red);
        s_ww[tid] = e / s;
        v  = rw0[tid];
        mx = bredMax(v, s_red);
        e  = expf(v - mx);
        s  = bredSum(e, s_red);
        s_rw[tid] = e / s;
    }

    for (int t = 0; t < Tt; t++){
        gbar();   // prev-step rd (and init) globally visible

        // ---- P1: ht = tanh([x_t, rd] @ Wc + bc). 256 CTAs: tile 32 rows x 32 cols ----
        {
            const int rb = cta >> 5;      // 8 rowblocks of 32
            const int cb = cta & 31;      // 32 colblocks of 32
            const float4* x4  = (const float4*)x;
            const float4* rd4 = (const float4*)g_rd;
            for (int i = tid; i < 32*64; i += NTHR){
                int r = i >> 6, q = i & 63;
                int row = rb*32 + r;
                float4 v;
                if (q < 32) v = x4[(t*Bb + row)*32 + q];
                else        v = __ldcg(&rd4[row*32 + (q - 32)]);
                *(float4*)&s_buf[r*SAS + q*4] = v;
            }
            __syncthreads();
            if (tid < 128){
                const int cq = tid & 7;        // col quad (8 quads = 32 cols)
                const int r0 = (tid >> 3) * 2; // 2 rows per thread
                const float4* W4 = (const float4*)Wc;
                const int c4 = cb*8 + cq;      // float4 col index (Wc row = 256 f4)
                float4 ac0 = make_float4(0,0,0,0), ac1 = make_float4(0,0,0,0);
                const float* a0p = &s_buf[r0*SAS];
                const float* a1p = a0p + SAS;
                #pragma unroll 8
                for (int k = 0; k < ICt; k++){
                    float a0 = a0p[k], a1 = a1p[k];
                    float4 w = W4[k*256 + c4];
                    ac0.x += a0*w.x; ac0.y += a0*w.y; ac0.z += a0*w.z; ac0.w += a0*w.w;
                    ac1.x += a1*w.x; ac1.y += a1*w.y; ac1.z += a1*w.z; ac1.w += a1*w.w;
                }
                float4 bi = ((const float4*)bc)[c4];
                float4 o0, o1;
                o0.x = tanhf(ac0.x + bi.x); o0.y = tanhf(ac0.y + bi.y);
                o0.z = tanhf(ac0.z + bi.z); o0.w = tanhf(ac0.w + bi.w);
                o1.x = tanhf(ac1.x + bi.x); o1.y = tanhf(ac1.y + bi.y);
                o1.z = tanhf(ac1.z + bi.z); o1.w = tanhf(ac1.w + bi.w);
                int row = rb*32 + r0;
                __stcg(((float4*)g_ht) + row*256 + c4,       o0);
                __stcg(((float4*)g_ht) + (row+1)*256 + c4,   o1);
            }
        }
        gbar();   // ht ready

        // ---- P2: [k_w|k_r|erase|add] = act(ht @ W + b), 128 GEMM CTAs; 128 GEMV CTAs ----
        if (cta < 128){
            const int rb = cta >> 4;      // 8 rowblocks of 32
            const int cb = cta & 15;      // 16 colblocks of 32 over 512 cols
            const int seg = cb >> 2;      // which weight matrix
            const float *Wp, *bp; float *op;
            if      (seg == 0){ Wp = Wk;          bp = bk;      op = g_k; }
            else if (seg == 1){ Wp = Wk + Hh*Mm;  bp = bk + Mm; op = g_k + Bb*Mm; }
            else if (seg == 2){ Wp = We;          bp = be;      op = g_e; }
            else              { Wp = Wa;          bp = ba;      op = g_a; }
            const float4* W4  = (const float4*)Wp;
            const float4* ht4 = (const float4*)g_ht;
            const int cq  = tid & 7;
            const int r0  = (tid >> 3) * 2;
            const int c4  = (cb & 3)*8 + cq;  // float4 col within 128-wide segment
            float4 ac0 = make_float4(0,0,0,0), ac1 = make_float4(0,0,0,0);
            for (int kc = 0; kc < 4; kc++){
                __syncthreads();
                for (int i = tid; i < 32*64; i += NTHR){
                    int rr = i >> 6, q = i & 63;
                    float4 v = __ldcg(&ht4[(rb*32 + rr)*256 + kc*64 + q]);
                    *(float4*)&s_buf[rr*SAS + q*4] = v;
                }
                __syncthreads();
                if (tid < 128){
                    const float* a0p = &s_buf[r0*SAS];
                    const float* a1p = a0p + SAS;
                    const int kb = kc*256;
                    #pragma unroll 8
                    for (int k = 0; k < 256; k++){
                        float a0 = a0p[k], a1 = a1p[k];
                        float4 w = W4[(kb + k)*32 + c4];
                        ac0.x += a0*w.x; ac0.y += a0*w.y; ac0.z += a0*w.z; ac0.w += a0*w.w;
                        ac1.x += a1*w.x; ac1.y += a1*w.y; ac1.z += a1*w.z; ac1.w += a1*w.w;
                    }
                }
            }
            if (tid < 128){
                float4 bi = ((const float4*)bp)[c4];
                ac0.x += bi.x; ac0.y += bi.y; ac0.z += bi.z; ac0.w += bi.w;
                ac1.x += bi.x; ac1.y += bi.y; ac1.z += bi.z; ac1.w += bi.w;
                float4 o0, o1;
                if (seg < 2){
                    o0.x = fmaxf(ac0.x,0.f); o0.y = fmaxf(ac0.y,0.f); o0.z = fmaxf(ac0.z,0.f); o0.w = fmaxf(ac0.w,0.f);
                    o1.x = fmaxf(ac1.x,0.f); o1.y = fmaxf(ac1.y,0.f); o1.z = fmaxf(ac1.z,0.f); o1.w = fmaxf(ac1.w,0.f);
                } else {
                    o0.x = sigmoidf_(ac0.x); o0.y = sigmoidf_(ac0.y); o0.z = sigmoidf_(ac0.z); o0.w = sigmoidf_(ac0.w);
                    o1.x = sigmoidf_(ac1.x); o1.y = sigmoidf_(ac1.y); o1.z = sigmoidf_(ac1.z); o1.w = sigmoidf_(ac1.w);
                }
                int row = rb*32 + r0;
                __stcg(((float4*)op) + row*32 + c4,     o0);
                __stcg(((float4*)op) + (row+1)*32 + c4, o1);
            }
        } else {
            // 12 scalar projections per batch: warp per (batch, channel)
            int gw = (cta - 128)*8 + wid;
            for (int job = gw; job < Bb*12; job += 128*8){
                int br = job / 12, c = job % 12;
                int hd = c / 6, cc = c % 6;
                const float* wp; float bi; int stride;
                if      (cc == 0){ wp = Wb   + hd*Hh;        bi = bb[hd];          stride = 1; }
                else if (cc == 1){ wp = Wg   + hd*Hh;        bi = bg[hd];          stride = 1; }
                else if (cc == 2){ wp = Wgam + hd*Hh;        bi = bgam[hd];        stride = 1; }
                else             { wp = Ws   + hd*Hh*3 + (cc-3); bi = bs[hd*3+cc-3]; stride = 3; }
                float acc = 0.f;
                for (int h = lane; h < Hh; h += 32)
                    acc += __ldcg(&g_ht[br*Hh + h]) * wp[h*stride];
                #pragma unroll
                for (int off = 16; off; off >>= 1) acc += __shfl_xor_sync(0xffffffffu, acc, off);
                if (lane == 0) __stcg(&g_small[br*12 + c], acc + bi);
            }
        }
        gbar();   // k / e / a / smalls ready

        // ---- P3 (CTA b): content addressing + gate + shift + sharpen, both heads ----
        {
            if (tid < 128){
                s_kw[tid] = __ldcg(&g_k[b*Mm + tid]);
                s_kr[tid] = __ldcg(&g_k[Bb*Mm + b*Mm + tid]);
                s_e[tid]  = __ldcg(&g_e[b*Mm + tid]);
                s_a[tid]  = __ldcg(&g_a[b*Mm + tid]);
            }
            if (tid < 12) s_sm[tid] = __ldcg(&g_small[b*12 + tid]);
            __syncthreads();
            // key norms
            {
                float v  = (tid < 128) ? s_kw[tid] : s_kr[tid - 128];
                float sq = v * v;
                #pragma unroll
                for (int off = 16; off; off >>= 1) sq += __shfl_xor_sync(0xffffffffu, sq, off);
                if (lane == 0) s_red[wid] = sq;
                __syncthreads();
                if (tid == 0){
                    s_red[32] = fmaxf(sqrtf(s_red[0]+s_red[1]+s_red[2]+s_red[3]), EPSf);
                    s_red[33] = fmaxf(sqrtf(s_red[4]+s_red[5]+s_red[6]+s_red[7]), EPSf);
                }
                __syncthreads();
            }
            const float ibw = softplusf(s_sm[0]) / s_red[32];   // beta_w / ||k_w||
            const float ibr = softplusf(s_sm[6]) / s_red[33];   // beta_r / ||k_r||
            __syncthreads();
            // pass A: cosine for both heads in one memory sweep (warp per row)
            {
                const float4* m4  = ((const float4*)g_mem) + b * (Nn*Mm/4);
                const float4  kw4 = ((float4*)s_kw)[lane];
                const float4  kr4 = ((float4*)s_kr)[lane];
                for (int j = 0; j < 32; j++){
                    int n = wid*32 + j;
                    float4 mv = m4[n*32 + lane];
                    float dw = mv.x*kw4.x + mv.y*kw4.y + mv.z*kw4.z + mv.w*kw4.w;
                    float dr = mv.x*kr4.x + mv.y*kr4.y + mv.z*kr4.z + mv.w*kr4.w;
                    float nn = mv.x*mv.x + mv.y*mv.y + mv.z*mv.z + mv.w*mv.w;
                    #pragma unroll
                    for (int off = 16; off; off >>= 1){
                        dw += __shfl_xor_sync(0xffffffffu, dw, off);
                        dr += __shfl_xor_sync(0xffffffffu, dr, off);
                        nn += __shfl_xor_sync(0xffffffffu, nn, off);
                    }
                    if (lane == 0){
                        float im = 1.f / fmaxf(sqrtf(nn), EPSf);
                        s_zw[n] = dw * ibw * im;
                        s_zr[n] = dr * ibr * im;
                    }
                }
                __syncthreads();
            }
            // per-head weight pipeline (n = tid)
            #pragma unroll 1
            for (int hd = 0; hd < 2; hd++){
                float* sz    = hd ? s_zr : s_zw;
                float* sprev = hd ? s_rw : s_ww;
                float graw = s_sm[hd*6 + 1];
                float gamr = s_sm[hd*6 + 2];
                float r0s  = s_sm[hd*6 + 3], r1s = s_sm[hd*6 + 4], r2s = s_sm[hd*6 + 5];
                float z  = sz[tid];
                float mx = bredMax(z, s_red);
                float ez = expf(z - mx);
                float sm = bredSum(ez, s_red);
                float wc = ez / sm;
                float g  = sigmoidf_(graw);
                s_tmp[tid] = g*wc + (1.f - g)*sprev[tid];
                __syncthreads();
                float m3 = fmaxf(r0s, fmaxf(r1s, r2s));
                float e0 = expf(r0s - m3), e1 = expf(r1s - m3), e2 = expf(r2s - m3);
                float i3 = 1.f / (e0 + e1 + e2);
                float wsh = e0*i3 * s_tmp[(tid + 255) & 255]
                          + e1*i3 * s_tmp[tid]
                          + e2*i3 * s_tmp[(tid + 1) & 255];
                float gamma = fmaxf(gamr, 0.f) + 1.f;
                float wpow  = powf(wsh, gamma);
                float tsum  = bredSum(wpow, s_red);   // also fences s_tmp reads before reuse
                sprev[tid]  = wpow / tsum;
            }
            __syncthreads();
        }

        // ---- P4 (CTA b): memory update + rd + out = rd @ Wo + bo ----
        {
            const int mq    = tid & 31;     // m-quad (float4) index, fixed per thread
            const int rbase = tid >> 5;
            const float4 e4 = ((float4*)s_e)[mq];
            const float4 a4 = ((float4*)s_a)[mq];
            float4* m4 = ((float4*)g_mem) + b * (Nn*Mm/4);
            float4 prd = make_float4(0,0,0,0);
            #pragma unroll 4
            for (int it = 0; it < 32; it++){
                int n = it*8 + rbase;
                float wwn = s_ww[n], rwn = s_rw[n];
                float4 mv = m4[n*32 + mq];
                float4 nv;
                nv.x = mv.x*(1.f - wwn*e4.x) + wwn*a4.x;
                nv.y = mv.y*(1.f - wwn*e4.y) + wwn*a4.y;
                nv.z = mv.z*(1.f - wwn*e4.z) + wwn*a4.z;
                nv.w = mv.w*(1.f - wwn*e4.w) + wwn*a4.w;
                m4[n*32 + mq] = nv;
                prd.x += rwn*nv.x; prd.y += rwn*nv.y; prd.z += rwn*nv.z; prd.w += rwn*nv.w;
            }
            s_prd[tid] = prd;
            __syncthreads();
            if (tid < 32){
                float4 r = s_prd[tid];
                #pragma unroll
                for (int j = 1; j < 8; j++){
                    float4 v = s_prd[tid + 32*j];
                    r.x += v.x; r.y += v.y; r.z += v.z; r.w += v.w;
                }
                ((float4*)s_rdv)[tid] = r;
                __stcg(((float4*)g_rd) + b*32 + tid, r);
            }
            __syncthreads();
            // out[t,b,:] = rd @ Wo + bo   (Wo: [M=128, I=128] row-major)
            {
                const int i = tid & 127, half = tid >> 7;
                float acc = 0.f;
                const float* Wor = Wo + half*64*Ii + i;
                const float* rr  = s_rdv + half*64;
                #pragma unroll 8
                for (int mm = 0; mm < 64; mm++) acc += rr[mm] * Wor[mm*Ii];
                s_tmp[tid] = acc;
                __syncthreads();
                if (tid < 128)
                    out[t*(Bb*Ii) + b*Ii + tid] = s_tmp[tid] + s_tmp[tid + 128] + bo[tid];
                __syncthreads();
            }
        }
    }
}

extern "C" void kernel_launch(void* const* d_in, const int* in_sizes, int n_in,
                              void* d_out, int out_size){
    (void)in_sizes; (void)n_in; (void)out_size;
    ntm_kernel<<<NCTA, NTHR>>>(
        (const float*)d_in[0],  (const float*)d_in[1],  (const float*)d_in[2],
        (const float*)d_in[3],  (const float*)d_in[4],  (const float*)d_in[5],
        (const float*)d_in[6],  (const float*)d_in[7],  (const float*)d_in[8],
        (const float*)d_in[9],  (const float*)d_in[10], (const float*)d_in[11],
        (const float*)d_in[12], (const float*)d_in[13], (const float*)d_in[14],
        (const float*)d_in[15], (const float*)d_in[16], (const float*)d_in[17],
        (const float*)d_in[18], (const float*)d_in[19], (const float*)d_in[20],
        (const float*)d_in[21], (const float*)d_in[22],
        (float*)d_out);
}

// round 8
// speedup vs baseline: 1.4481x; 1.4481x over previous
#include <cuda_runtime.h>
#include <math.h>

#define Tt 64
#define Bb 256
#define Nn 256
#define Mm 128
#define Hh 1024
#define Ii 128
#define ICt 256
#define EPSf 1e-8f
#define NCTA 256
#define NTHR 256
#define SAS 260   // smem A-tile row stride (floats): 260%32==4 -> bank-spread, %4==0 -> float4 ok

// ---------------- persistent device scratch ----------------
__device__ __align__(16) float g_mem[Bb*Nn*Mm];   // 33.5 MB, L2-resident
__device__ __align__(16) float g_ht [Bb*Hh];
__device__ __align__(16) float g_k  [2*Bb*Mm];
__device__ __align__(16) float g_e  [Bb*Mm];
__device__ __align__(16) float g_a  [Bb*Mm];
__device__ __align__(16) float g_rd [Bb*Mm];
__device__            float g_small[Bb*12];
__device__ unsigned g_barcnt;
__device__ volatile unsigned g_bargen;

// ---------------- grid barrier (all 256 CTAs co-resident) ----------------
__device__ __forceinline__ void gbar(){
    __threadfence();
    __syncthreads();
    if (threadIdx.x == 0){
        unsigned gen = g_bargen;
        if (atomicAdd(&g_barcnt, 1u) == NCTA - 1u){
            g_barcnt = 0u;
            __threadfence();
            g_bargen = gen + 1u;
        } else {
            while (g_bargen == gen) { __nanosleep(64); }
        }
        __threadfence();
    }
    __syncthreads();
}

// ---------------- block reductions over 256 threads ----------------
__device__ __forceinline__ float bredSum(float v, float* s_red){
    int lane = threadIdx.x & 31, wid = threadIdx.x >> 5;
    #pragma unroll
    for (int off = 16; off; off >>= 1) v += __shfl_xor_sync(0xffffffffu, v, off);
    if (lane == 0) s_red[wid] = v;
    __syncthreads();
    if (threadIdx.x == 0){
        float s = 0.f;
        #pragma unroll
        for (int j = 0; j < 8; j++) s += s_red[j];
        s_red[32] = s;
    }
    __syncthreads();
    return s_red[32];
}
__device__ __forceinline__ float bredMax(float v, float* s_red){
    int lane = threadIdx.x & 31, wid = threadIdx.x >> 5;
    #pragma unroll
    for (int off = 16; off; off >>= 1) v = fmaxf(v, __shfl_xor_sync(0xffffffffu, v, off));
    if (lane == 0) s_red[wid] = v;
    __syncthreads();
    if (threadIdx.x == 0){
        float s = -3.4e38f;
        #pragma unroll
        for (int j = 0; j < 8; j++) s = fmaxf(s, s_red[j]);
        s_red[32] = s;
    }
    __syncthreads();
    return s_red[32];
}

__device__ __forceinline__ float softplusf(float x){
    return fmaxf(x, 0.f) + log1pf(expf(-fabsf(x)));
}
__device__ __forceinline__ float sigmoidf_(float x){
    return 1.f / (1.f + expf(-x));
}

// ---------------- the persistent NTM kernel ----------------
__global__ void __launch_bounds__(NTHR, 2) ntm_kernel(
    const float* __restrict__ x,
    const float* __restrict__ Wc,   const float* __restrict__ bc,
    const float* __restrict__ Wk,   const float* __restrict__ bk,
    const float* __restrict__ Wb,   const float* __restrict__ bb,
    const float* __restrict__ Wg,   const float* __restrict__ bg,
    const float* __restrict__ Ws,   const float* __restrict__ bs,
    const float* __restrict__ Wgam, const float* __restrict__ bgam,
    const float* __restrict__ We,   const float* __restrict__ be,
    const float* __restrict__ Wa,   const float* __restrict__ ba,
    const float* __restrict__ Wo,   const float* __restrict__ bo,
    const float* __restrict__ memory0,
    const float* __restrict__ ww0,  const float* __restrict__ rw0,
    const float* __restrict__ read0,
    float* __restrict__ out)
{
    __shared__ __align__(16) float s_buf[32*SAS];   // 33.3 KB: GEMM A-tile, reused as P3/P4 scratch
    __shared__ float s_ww[Nn];
    __shared__ float s_rw[Nn];
    __shared__ float s_red[40];

    const int tid  = threadIdx.x;
    const int cta  = blockIdx.x;
    const int b    = cta;
    const int wid  = tid >> 5, lane = tid & 31;

    // P3/P4 scratch carve (inside s_buf; all offsets float4-safe)
    float*  s_kw  = s_buf;            // 128
    float*  s_kr  = s_buf + 128;      // 128
    float*  s_e   = s_buf + 256;      // 128
    float*  s_a   = s_buf + 384;      // 128
    float*  s_sm  = s_buf + 512;      // 16
    float4* s_prd = (float4*)(s_buf + 1024);  // 256 float4
    float*  s_zw  = s_buf + 2048;     // 256
    float*  s_zr  = s_buf + 2304;     // 256
    float*  s_tmp = s_buf + 2560;     // 256
    float*  s_rdv = s_buf + 2816;     // 128

    // ---------------- init ----------------
    {
        float4*       md = ((float4*)g_mem) + b * (Nn*Mm/4);
        const float4* ms = (const float4*)memory0;
        for (int i = tid; i < Nn*Mm/4; i += NTHR) md[i] = ms[i];
        if (tid < Mm) __stcg(&g_rd[b*Mm + tid], read0[tid]);
        float v  = ww0[tid];
        float mx = bredMax(v, s_red);
        float e  = expf(v - mx);
        float s  = bredSum(e, s_red);
        s_ww[tid] = e / s;
        v  = rw0[tid];
        mx = bredMax(v, s_red);
        e  = expf(v - mx);
        s  = bredSum(e, s_red);
        s_rw[tid] = e / s;
    }

    for (int t = 0; t < Tt; t++){
        gbar();   // prev-step rd (and init) globally visible

        // ---- P1: ht = tanh([x_t, rd] @ Wc + bc). 256 CTAs: tile 32 rows x 32 cols ----
        {
            const int rb = cta >> 5;      // 8 rowblocks of 32
            const int cb = cta & 31;      // 32 colblocks of 32
            const float4* x4  = (const float4*)x;
            const float4* rd4 = (const float4*)g_rd;
            for (int i = tid; i < 32*64; i += NTHR){
                int r = i >> 6, q = i & 63;
                int row = rb*32 + r;
                float4 v;
                if (q < 32) v = x4[(t*Bb + row)*32 + q];
                else        v = __ldcg(&rd4[row*32 + (q - 32)]);
                *(float4*)&s_buf[r*SAS + q*4] = v;
            }
            __syncthreads();
            if (tid < 128){
                const int cq = tid & 7;        // col quad (8 quads = 32 cols)
                const int r0 = (tid >> 3) * 2; // 2 rows per thread
                const float4* W4 = (const float4*)Wc;
                const int c4 = cb*8 + cq;      // float4 col index (Wc row = 256 f4)
                float4 ac0 = make_float4(0,0,0,0), ac1 = make_float4(0,0,0,0);
                const float* a0p = &s_buf[r0*SAS];
                const float* a1p = a0p + SAS;
                #pragma unroll 8
                for (int k = 0; k < ICt; k++){
                    float a0 = a0p[k], a1 = a1p[k];
                    float4 w = W4[k*256 + c4];
                    ac0.x += a0*w.x; ac0.y += a0*w.y; ac0.z += a0*w.z; ac0.w += a0*w.w;
                    ac1.x += a1*w.x; ac1.y += a1*w.y; ac1.z += a1*w.z; ac1.w += a1*w.w;
                }
                float4 bi = ((const float4*)bc)[c4];
                float4 o0, o1;
                o0.x = tanhf(ac0.x + bi.x); o0.y = tanhf(ac0.y + bi.y);
                o0.z = tanhf(ac0.z + bi.z); o0.w = tanhf(ac0.w + bi.w);
                o1.x = tanhf(ac1.x + bi.x); o1.y = tanhf(ac1.y + bi.y);
                o1.z = tanhf(ac1.z + bi.z); o1.w = tanhf(ac1.w + bi.w);
                int row = rb*32 + r0;
                __stcg(((float4*)g_ht) + row*256 + c4,       o0);
                __stcg(((float4*)g_ht) + (row+1)*256 + c4,   o1);
            }
        }
        gbar();   // ht ready

        // ---- P2: [k_w|k_r|erase|add] = act(ht @ W + b), 128 GEMM CTAs; 128 GEMV CTAs ----
        if (cta < 128){
            const int rb = cta >> 4;      // 8 rowblocks of 32
            const int cb = cta & 15;      // 16 colblocks of 32 over 512 cols
            const int seg = cb >> 2;      // which weight matrix
            const float *Wp, *bp; float *op;
            if      (seg == 0){ Wp = Wk;          bp = bk;      op = g_k; }
            else if (seg == 1){ Wp = Wk + Hh*Mm;  bp = bk + Mm; op = g_k + Bb*Mm; }
            else if (seg == 2){ Wp = We;          bp = be;      op = g_e; }
            else              { Wp = Wa;          bp = ba;      op = g_a; }
            const float4* W4  = (const float4*)Wp;
            const float4* ht4 = (const float4*)g_ht;
            const int cq  = tid & 7;
            const int r0  = (tid >> 3) * 2;
            const int c4  = (cb & 3)*8 + cq;  // float4 col within 128-wide segment
            float4 ac0 = make_float4(0,0,0,0), ac1 = make_float4(0,0,0,0);
            for (int kc = 0; kc < 4; kc++){
                __syncthreads();
                for (int i = tid; i < 32*64; i += NTHR){
                    int rr = i >> 6, q = i & 63;
                    float4 v = __ldcg(&ht4[(rb*32 + rr)*256 + kc*64 + q]);
                    *(float4*)&s_buf[rr*SAS + q*4] = v;
                }
                __syncthreads();
                if (tid < 128){
                    const float* a0p = &s_buf[r0*SAS];
                    const float* a1p = a0p + SAS;
                    const int kb = kc*256;
                    #pragma unroll 8
                    for (int k = 0; k < 256; k++){
                        float a0 = a0p[k], a1 = a1p[k];
                        float4 w = W4[(kb + k)*32 + c4];
                        ac0.x += a0*w.x; ac0.y += a0*w.y; ac0.z += a0*w.z; ac0.w += a0*w.w;
                        ac1.x += a1*w.x; ac1.y += a1*w.y; ac1.z += a1*w.z; ac1.w += a1*w.w;
                    }
                }
            }
            if (tid < 128){
                float4 bi = ((const float4*)bp)[c4];
                ac0.x += bi.x; ac0.y += bi.y; ac0.z += bi.z; ac0.w += bi.w;
                ac1.x += bi.x; ac1.y += bi.y; ac1.z += bi.z; ac1.w += bi.w;
                float4 o0, o1;
                if (seg < 2){
                    o0.x = fmaxf(ac0.x,0.f); o0.y = fmaxf(ac0.y,0.f); o0.z = fmaxf(ac0.z,0.f); o0.w = fmaxf(ac0.w,0.f);
                    o1.x = fmaxf(ac1.x,0.f); o1.y = fmaxf(ac1.y,0.f); o1.z = fmaxf(ac1.z,0.f); o1.w = fmaxf(ac1.w,0.f);
                } else {
                    o0.x = sigmoidf_(ac0.x); o0.y = sigmoidf_(ac0.y); o0.z = sigmoidf_(ac0.z); o0.w = sigmoidf_(ac0.w);
                    o1.x = sigmoidf_(ac1.x); o1.y = sigmoidf_(ac1.y); o1.z = sigmoidf_(ac1.z); o1.w = sigmoidf_(ac1.w);
                }
                int row = rb*32 + r0;
                __stcg(((float4*)op) + row*32 + c4,     o0);
                __stcg(((float4*)op) + (row+1)*32 + c4, o1);
            }
        } else {
            // 12 scalar projections per batch: warp per (batch, channel)
            int gw = (cta - 128)*8 + wid;
            for (int job = gw; job < Bb*12; job += 128*8){
                int br = job / 12, c = job % 12;
                int hd = c / 6, cc = c % 6;
                const float* wp; float bi; int stride;
                if      (cc == 0){ wp = Wb   + hd*Hh;        bi = bb[hd];          stride = 1; }
                else if (cc == 1){ wp = Wg   + hd*Hh;        bi = bg[hd];          stride = 1; }
                else if (cc == 2){ wp = Wgam + hd*Hh;        bi = bgam[hd];        stride = 1; }
                else             { wp = Ws   + hd*Hh*3 + (cc-3); bi = bs[hd*3+cc-3]; stride = 3; }
                float acc = 0.f;
                for (int h = lane; h < Hh; h += 32)
                    acc += __ldcg(&g_ht[br*Hh + h]) * wp[h*stride];
                #pragma unroll
                for (int off = 16; off; off >>= 1) acc += __shfl_xor_sync(0xffffffffu, acc, off);
                if (lane == 0) __stcg(&g_small[br*12 + c], acc + bi);
            }
        }
        gbar();   // k / e / a / smalls ready

        // ---- P3 (CTA b): content addressing + gate + shift + sharpen, both heads ----
        {
            if (tid < 128){
                s_kw[tid] = __ldcg(&g_k[b*Mm + tid]);
                s_kr[tid] = __ldcg(&g_k[Bb*Mm + b*Mm + tid]);
                s_e[tid]  = __ldcg(&g_e[b*Mm + tid]);
                s_a[tid]  = __ldcg(&g_a[b*Mm + tid]);
            }
            if (tid < 12) s_sm[tid] = __ldcg(&g_small[b*12 + tid]);
            __syncthreads();
            // key norms
            {
                float v  = (tid < 128) ? s_kw[tid] : s_kr[tid - 128];
                float sq = v * v;
                #pragma unroll
                for (int off = 16; off; off >>= 1) sq += __shfl_xor_sync(0xffffffffu, sq, off);
                if (lane == 0) s_red[wid] = sq;
                __syncthreads();
                if (tid == 0){
                    s_red[32] = fmaxf(sqrtf(s_red[0]+s_red[1]+s_red[2]+s_red[3]), EPSf);
                    s_red[33] = fmaxf(sqrtf(s_red[4]+s_red[5]+s_red[6]+s_red[7]), EPSf);
                }
                __syncthreads();
            }
            const float ibw = softplusf(s_sm[0]) / s_red[32];   // beta_w / ||k_w||
            const float ibr = softplusf(s_sm[6]) / s_red[33];   // beta_r / ||k_r||
            __syncthreads();
            // pass A: cosine for both heads in one memory sweep (warp per row)
            {
                const float4* m4  = ((const float4*)g_mem) + b * (Nn*Mm/4);
                const float4  kw4 = ((float4*)s_kw)[lane];
                const float4  kr4 = ((float4*)s_kr)[lane];
                for (int j = 0; j < 32; j++){
                    int n = wid*32 + j;
                    float4 mv = m4[n*32 + lane];
                    float dw = mv.x*kw4.x + mv.y*kw4.y + mv.z*kw4.z + mv.w*kw4.w;
                    float dr = mv.x*kr4.x + mv.y*kr4.y + mv.z*kr4.z + mv.w*kr4.w;
                    float nn = mv.x*mv.x + mv.y*mv.y + mv.z*mv.z + mv.w*mv.w;
                    #pragma unroll
                    for (int off = 16; off; off >>= 1){
                        dw += __shfl_xor_sync(0xffffffffu, dw, off);
                        dr += __shfl_xor_sync(0xffffffffu, dr, off);
                        nn += __shfl_xor_sync(0xffffffffu, nn, off);
                    }
                    if (lane == 0){
                        float im = 1.f / fmaxf(sqrtf(nn), EPSf);
                        s_zw[n] = dw * ibw * im;
                        s_zr[n] = dr * ibr * im;
                    }
                }
                __syncthreads();
            }
            // per-head weight pipeline (n = tid)
            #pragma unroll 1
            for (int hd = 0; hd < 2; hd++){
                float* sz    = hd ? s_zr : s_zw;
                float* sprev = hd ? s_rw : s_ww;
                float graw = s_sm[hd*6 + 1];
                float gamr = s_sm[hd*6 + 2];
                float r0s  = s_sm[hd*6 + 3], r1s = s_sm[hd*6 + 4], r2s = s_sm[hd*6 + 5];
                float z  = sz[tid];
                float mx = bredMax(z, s_red);
                float ez = expf(z - mx);
                float sm = bredSum(ez, s_red);
                float wc = ez / sm;
                float g  = sigmoidf_(graw);
                s_tmp[tid] = g*wc + (1.f - g)*sprev[tid];
                __syncthreads();
                float m3 = fmaxf(r0s, fmaxf(r1s, r2s));
                float e0 = expf(r0s - m3), e1 = expf(r1s - m3), e2 = expf(r2s - m3);
                float i3 = 1.f / (e0 + e1 + e2);
                float wsh = e0*i3 * s_tmp[(tid + 255) & 255]
                          + e1*i3 * s_tmp[tid]
                          + e2*i3 * s_tmp[(tid + 1) & 255];
                float gamma = fmaxf(gamr, 0.f) + 1.f;
                float wpow  = powf(wsh, gamma);
                float tsum  = bredSum(wpow, s_red);   // also fences s_tmp reads before reuse
                sprev[tid]  = wpow / tsum;
            }
            __syncthreads();
        }

        // ---- P4 (CTA b): memory update + rd + out = rd @ Wo + bo ----
        {
            const int mq    = tid & 31;     // m-quad (float4) index, fixed per thread
            const int rbase = tid >> 5;
            const float4 e4 = ((float4*)s_e)[mq];
            const float4 a4 = ((float4*)s_a)[mq];
            float4* m4 = ((float4*)g_mem) + b * (Nn*Mm/4);
            float4 prd = make_float4(0,0,0,0);
            #pragma unroll 4
            for (int it = 0; it < 32; it++){
                int n = it*8 + rbase;
                float wwn = s_ww[n], rwn = s_rw[n];
                float4 mv = m4[n*32 + mq];
                float4 nv;
                nv.x = mv.x*(1.f - wwn*e4.x) + wwn*a4.x;
                nv.y = mv.y*(1.f - wwn*e4.y) + wwn*a4.y;
                nv.z = mv.z*(1.f - wwn*e4.z) + wwn*a4.z;
                nv.w = mv.w*(1.f - wwn*e4.w) + wwn*a4.w;
                m4[n*32 + mq] = nv;
                prd.x += rwn*nv.x; prd.y += rwn*nv.y; prd.z += rwn*nv.z; prd.w += rwn*nv.w;
            }
            s_prd[tid] = prd;
            __syncthreads();
            if (tid < 32){
                float4 r = s_prd[tid];
                #pragma unroll
                for (int j = 1; j < 8; j++){
                    float4 v = s_prd[tid + 32*j];
                    r.x += v.x; r.y += v.y; r.z += v.z; r.w += v.w;
                }
                ((float4*)s_rdv)[tid] = r;
                __stcg(((float4*)g_rd) + b*32 + tid, r);
            }
            __syncthreads();
            // out[t,b,:] = rd @ Wo + bo   (Wo: [M=128, I=128] row-major)
            {
                const int i = tid & 127, half = tid >> 7;
                float acc = 0.f;
                const float* Wor = Wo + half*64*Ii + i;
                const float* rr  = s_rdv + half*64;
                #pragma unroll 8
                for (int mm = 0; mm < 64; mm++) acc += rr[mm] * Wor[mm*Ii];
                s_tmp[tid] = acc;
                __syncthreads();
                if (tid < 128)
                    out[t*(Bb*Ii) + b*Ii + tid] = s_tmp[tid] + s_tmp[tid + 128] + bo[tid];
                __syncthreads();
            }
        }
    }
}

extern "C" void kernel_launch(void* const* d_in, const int* in_sizes, int n_in,
                              void* d_out, int out_size){
    (void)in_sizes; (void)n_in; (void)out_size;
    ntm_kernel<<<NCTA, NTHR>>>(
        (const float*)d_in[0],  (const float*)d_in[1],  (const float*)d_in[2],
        (const float*)d_in[3],  (const float*)d_in[4],  (const float*)d_in[5],
        (const float*)d_in[6],  (const float*)d_in[7],  (const float*)d_in[8],
        (const float*)d_in[9],  (const float*)d_in[10], (const float*)d_in[11],
        (const float*)d_in[12], (const float*)d_in[13], (const float*)d_in[14],
        (const float*)d_in[15], (const float*)d_in[16], (const float*)d_in[17],
        (const float*)d_in[18], (const float*)d_in[19], (const float*)d_in[20],
        (const float*)d_in[21], (const float*)d_in[22],
        (float*)d_out);
}

// round 9
// speedup vs baseline: 2.0908x; 1.4438x over previous
#include <cuda_runtime.h>
#include <math.h>

#define Tt 64
#define Bb 256
#define Nn 256
#define Mm 128
#define Hh 1024
#define Ii 128
#define ICt 256
#define EPSf 1e-8f
#define NCTA 256
#define NTHR 256

#define SBUF 8448      // floats
#define SAS1 264       // P1 A-tile row stride (32 rows x 264 = 8448)
#define SAS2 524       // P2 A-tile row stride (16 rows x 524 = 8384)

// ---------------- persistent device scratch ----------------
__device__ __align__(16) float g_mem[Bb*Nn*Mm];   // 33.5 MB, L2-resident
__device__ __align__(16) float g_ht [Bb*Hh];
__device__ __align__(16) float g_k  [2*Bb*Mm];
__device__ __align__(16) float g_e  [Bb*Mm];
__device__ __align__(16) float g_a  [Bb*Mm];
__device__ __align__(16) float g_rd [Bb*Mm];
__device__ unsigned g_barcnt;
__device__ volatile unsigned g_bargen;

// ---------------- f32x2 packed math (sm_103a FFMA2 path) ----------------
__device__ __forceinline__ unsigned long long pk2(float a){
    unsigned long long r;
    asm("mov.b64 %0,{%1,%1};" : "=l"(r) : "f"(a));
    return r;
}
__device__ __forceinline__ void f2fma(unsigned long long& c, unsigned long long a, unsigned long long b){
    asm("fma.rn.f32x2 %0,%1,%2,%0;" : "+l"(c) : "l"(a), "l"(b));
}
__device__ __forceinline__ unsigned long long ad2(unsigned long long a, unsigned long long b){
    unsigned long long r;
    asm("add.rn.f32x2 %0,%1,%2;" : "=l"(r) : "l"(a), "l"(b));
    return r;
}
__device__ __forceinline__ float2 up2(unsigned long long v){
    float2 f;
    asm("mov.b64 {%0,%1},%2;" : "=f"(f.x), "=f"(f.y) : "l"(v));
    return f;
}

// ---------------- grid barrier (all 256 CTAs co-resident) ----------------
__device__ __forceinline__ void gbar(){
    __threadfence();
    __syncthreads();
    if (threadIdx.x == 0){
        unsigned gen = g_bargen;
        if (atomicAdd(&g_barcnt, 1u) == NCTA - 1u){
            g_barcnt = 0u;
            __threadfence();
            g_bargen = gen + 1u;
        } else {
            while (g_bargen == gen) { __nanosleep(64); }
        }
        __threadfence();
    }
    __syncthreads();
}

// ---------------- block reductions over 256 threads ----------------
__device__ __forceinline__ float bredSum(float v, float* s_red){
    int lane = threadIdx.x & 31, wid = threadIdx.x >> 5;
    #pragma unroll
    for (int off = 16; off; off >>= 1) v += __shfl_xor_sync(0xffffffffu, v, off);
    if (lane == 0) s_red[wid] = v;
    __syncthreads();
    if (threadIdx.x == 0){
        float s = 0.f;
        #pragma unroll
        for (int j = 0; j < 8; j++) s += s_red[j];
        s_red[32] = s;
    }
    __syncthreads();
    return s_red[32];
}
__device__ __forceinline__ float bredMax(float v, float* s_red){
    int lane = threadIdx.x & 31, wid = threadIdx.x >> 5;
    #pragma unroll
    for (int off = 16; off; off >>= 1) v = fmaxf(v, __shfl_xor_sync(0xffffffffu, v, off));
    if (lane == 0) s_red[wid] = v;
    __syncthreads();
    if (threadIdx.x == 0){
        float s = -3.4e38f;
        #pragma unroll
        for (int j = 0; j < 8; j++) s = fmaxf(s, s_red[j]);
        s_red[32] = s;
    }
    __syncthreads();
    return s_red[32];
}

__device__ __forceinline__ float softplusf(float x){
    return fmaxf(x, 0.f) + log1pf(expf(-fabsf(x)));
}
__device__ __forceinline__ float sigmoidf_(float x){
    return 1.f / (1.f + expf(-x));
}

// ---------------- the persistent NTM kernel ----------------
__global__ void __launch_bounds__(NTHR, 2) ntm_kernel(
    const float* __restrict__ x,
    const float* __restrict__ Wc,   const float* __restrict__ bc,
    const float* __restrict__ Wk,   const float* __restrict__ bk,
    const float* __restrict__ Wb,   const float* __restrict__ bb,
    const float* __restrict__ Wg,   const float* __restrict__ bg,
    const float* __restrict__ Ws,   const float* __restrict__ bs,
    const float* __restrict__ Wgam, const float* __restrict__ bgam,
    const float* __restrict__ We,   const float* __restrict__ be,
    const float* __restrict__ Wa,   const float* __restrict__ ba,
    const float* __restrict__ Wo,   const float* __restrict__ bo,
    const float* __restrict__ memory0,
    const float* __restrict__ ww0,  const float* __restrict__ rw0,
    const float* __restrict__ read0,
    float* __restrict__ out)
{
    __shared__ __align__(16) float s_buf[SBUF];
    __shared__ float s_ww[Nn];
    __shared__ float s_rw[Nn];
    __shared__ float s_red[40];
    __shared__ float s_sm[16];

    const int tid  = threadIdx.x;
    const int cta  = blockIdx.x;
    const int b    = cta;
    const int wid  = tid >> 5, lane = tid & 31;

    // ------- per-CTA constants (hoisted) -------
    // P1: 8 rowblocks x 32 colblocks over [256, 1024]
    const int RB1 = cta >> 5, CB1 = cta & 31;
    const int t7  = tid & 127, ks1 = tid >> 7;     // P1 k-split 2
    const int cq1 = t7 & 7,   rp1 = t7 >> 3;       // 8 col-quads, 16 row-pairs
    const int c4g1 = CB1*8 + cq1;                  // f4 col index in 1024-wide Wc row
    // P2: 16 rowblocks x 16 colblocks over [256, 512]
    const int RB2 = cta >> 4, CB2 = cta & 15;
    const int seg = CB2 >> 2;
    const int t6  = tid & 63, g4 = tid >> 6;       // P2 k-split 4
    const int cq2 = t6 & 7,   rp2 = t6 >> 3;       // 8 col-quads, 8 row-pairs
    const int c4s = (CB2 & 3)*8 + cq2;             // f4 col within 128-wide segment
    const float *Wp2, *bp2; float *op2;
    if      (seg == 0){ Wp2 = Wk;          bp2 = bk;      op2 = g_k; }
    else if (seg == 1){ Wp2 = Wk + Hh*Mm;  bp2 = bk + Mm; op2 = g_k + Bb*Mm; }
    else if (seg == 2){ Wp2 = We;          bp2 = be;      op2 = g_e; }
    else              { Wp2 = Wa;          bp2 = ba;      op2 = g_a; }
    const unsigned long long* __restrict__ Wc2 = (const unsigned long long*)Wc;
    const unsigned long long* __restrict__ Wq2 = (const unsigned long long*)Wp2;

    // P3/P4 scratch carve inside s_buf (dead outside P3/P4)
    float*  s_kw  = s_buf;                 // 128
    float*  s_kr  = s_buf + 128;           // 128
    float*  s_e   = s_buf + 256;           // 128
    float*  s_a   = s_buf + 384;           // 128
    float*  s_zw  = s_buf + 512;           // 256
    float*  s_zr  = s_buf + 768;           // 256
    float*  s_tmp = s_buf + 1024;          // 256
    float4* s_prd = (float4*)(s_buf + 1536); // 256 f4

    // ---------------- init ----------------
    {
        float4*       md = ((float4*)g_mem) + b * (Nn*Mm/4);
        const float4* ms = (const float4*)memory0;
        for (int i = tid; i < Nn*Mm/4; i += NTHR) md[i] = ms[i];
        if (tid < Mm) __stcg(&g_rd[b*Mm + tid], read0[tid]);
        float v  = ww0[tid];
        float mx = bredMax(v, s_red);
        float e  = expf(v - mx);
        float s  = bredSum(e, s_red);
        s_ww[tid] = e / s;
        v  = rw0[tid];
        mx = bredMax(v, s_red);
        e  = expf(v - mx);
        s  = bredSum(e, s_red);
        s_rw[tid] = e / s;
    }

    for (int t = 0; t < Tt; t++){
        gbar();   // prev-step rd globally visible

        // ================= P1: ht = tanh([x_t, rd] @ Wc + bc) =================
        // tile 32 rows x 32 cols, k=256, k-split 2, FFMA2 microkernel
        {
            const float4* x4  = (const float4*)x;
            const float4* rd4 = (const float4*)g_rd;
            for (int i = tid; i < 32*64; i += NTHR){
                int r = i >> 6, q = i & 63;
                int row = RB1*32 + r;
                float4 v;
                if (q < 32) v = x4[(t*Bb + row)*32 + q];
                else        v = __ldcg(&rd4[row*32 + (q - 32)]);
                *(float4*)&s_buf[r*SAS1 + q*4] = v;
            }
            __syncthreads();

            unsigned long long A00=0ull, A01=0ull, A10=0ull, A11=0ull;
            {
                const float* a0p = s_buf + (rp1*2)*SAS1 + ks1*128;
                const float* a1p = a0p + SAS1;
                const ulonglong2* wp = ((const ulonglong2*)Wc2) + (ks1*128)*256 + c4g1;
                #pragma unroll 8
                for (int kk = 0; kk < 128; kk++){
                    float a0 = a0p[kk], a1 = a1p[kk];
                    ulonglong2 w = __ldg(&wp[kk*256]);
                    unsigned long long p0 = pk2(a0), p1 = pk2(a1);
                    f2fma(A00, p0, w.x); f2fma(A01, p0, w.y);
                    f2fma(A10, p1, w.x); f2fma(A11, p1, w.y);
                }
            }

            // out[t-1] = rd_{t-1} @ Wo + bo : rd lives at A-tile cols 128..255
            if (t > 0 && tid < 128){
                int r = tid >> 2, c = tid & 3;
                int col = CB1*4 + c;
                const float* ap = s_buf + r*SAS1 + 128;
                float acc = 0.f;
                #pragma unroll 8
                for (int m = 0; m < 128; m++)
                    acc += ap[m] * __ldg(&Wo[m*Ii + col]);
                out[(t-1)*(Bb*Ii) + (RB1*32 + r)*Ii + col] = acc + bo[col];
            }
            __syncthreads();   // A-tile reads complete

            unsigned long long* pp = (unsigned long long*)s_buf;
            if (ks1 == 1){
                pp[t7*4+0]=A00; pp[t7*4+1]=A01; pp[t7*4+2]=A10; pp[t7*4+3]=A11;
            }
            __syncthreads();
            if (ks1 == 0){
                A00 = ad2(A00, pp[t7*4+0]); A01 = ad2(A01, pp[t7*4+1]);
                A10 = ad2(A10, pp[t7*4+2]); A11 = ad2(A11, pp[t7*4+3]);
                float2 v00 = up2(A00), v01 = up2(A01), v10 = up2(A10), v11 = up2(A11);
                float4 bi = __ldg(((const float4*)bc) + c4g1);
                float4 o0 = make_float4(tanhf(v00.x+bi.x), tanhf(v00.y+bi.y),
                                        tanhf(v01.x+bi.z), tanhf(v01.y+bi.w));
                float4 o1 = make_float4(tanhf(v10.x+bi.x), tanhf(v10.y+bi.y),
                                        tanhf(v11.x+bi.z), tanhf(v11.y+bi.w));
                int row = RB1*32 + rp1*2;
                __stcg(((float4*)g_ht) + row*256 + c4g1,     o0);
                __stcg(((float4*)g_ht) + (row+1)*256 + c4g1, o1);
            }
        }
        gbar();   // ht ready

        // ===== P2: [k_w|k_r|erase|add] = act(ht @ W + b), all 256 CTAs =====
        // tile 16 rows x 32 cols, k=1024 in 2 staged chunks, k-split 4
        {
            unsigned long long A00=0ull, A01=0ull, A10=0ull, A11=0ull;
            const float4* ht4 = (const float4*)g_ht;
            for (int ch = 0; ch < 2; ch++){
                __syncthreads();
                for (int i = tid; i < 16*128; i += NTHR){
                    int r = i >> 7, q = i & 127;
                    float4 v = __ldcg(&ht4[(RB2*16 + r)*256 + ch*128 + q]);
                    *(float4*)&s_buf[r*SAS2 + q*4] = v;
                }
                __syncthreads();
                const float* a0p = s_buf + (rp2*2)*SAS2 + g4*128;
                const float* a1p = a0p + SAS2;
                const ulonglong2* wp = ((const ulonglong2*)Wq2) + (ch*512 + g4*128)*32 + c4s;
                #pragma unroll 8
                for (int kk = 0; kk < 128; kk++){
                    float a0 = a0p[kk], a1 = a1p[kk];
                    ulonglong2 w = __ldg(&wp[kk*32]);
                    unsigned long long p0 = pk2(a0), p1 = pk2(a1);
                    f2fma(A00, p0, w.x); f2fma(A01, p0, w.y);
                    f2fma(A10, p1, w.x); f2fma(A11, p1, w.y);
                }
            }
            __syncthreads();
            unsigned long long* pp = (unsigned long long*)s_buf;
            if (g4 > 0){
                int base = ((g4-1)*64 + t6)*4;
                pp[base]=A00; pp[base+1]=A01; pp[base+2]=A10; pp[base+3]=A11;
            }
            __syncthreads();
            if (g4 == 0){
                #pragma unroll
                for (int gg = 0; gg < 3; gg++){
                    int base = (gg*64 + t6)*4;
                    A00 = ad2(A00, pp[base]);   A01 = ad2(A01, pp[base+1]);
                    A10 = ad2(A10, pp[base+2]); A11 = ad2(A11, pp[base+3]);
                }
                float2 v00 = up2(A00), v01 = up2(A01), v10 = up2(A10), v11 = up2(A11);
                float4 bi = __ldg(((const float4*)bp2) + c4s);
                float4 o0, o1;
                if (seg < 2){
                    o0 = make_float4(fmaxf(v00.x+bi.x,0.f), fmaxf(v00.y+bi.y,0.f),
                                     fmaxf(v01.x+bi.z,0.f), fmaxf(v01.y+bi.w,0.f));
                    o1 = make_float4(fmaxf(v10.x+bi.x,0.f), fmaxf(v10.y+bi.y,0.f),
                                     fmaxf(v11.x+bi.z,0.f), fmaxf(v11.y+bi.w,0.f));
                } else {
                    o0 = make_float4(sigmoidf_(v00.x+bi.x), sigmoidf_(v00.y+bi.y),
                                     sigmoidf_(v01.x+bi.z), sigmoidf_(v01.y+bi.w));
                    o1 = make_float4(sigmoidf_(v10.x+bi.x), sigmoidf_(v10.y+bi.y),
                                     sigmoidf_(v11.x+bi.z), sigmoidf_(v11.y+bi.w));
                }
                int row = RB2*16 + rp2*2;
                __stcg(((float4*)op2) + row*32 + c4s,     o0);
                __stcg(((float4*)op2) + (row+1)*32 + c4s, o1);
            }
        }
        gbar();   // k / e / a ready

        // ===== P3 (CTA b): smalls + content addressing + gate/shift/sharpen =====
        {
            if (tid < 128){
                s_kw[tid] = __ldcg(&g_k[b*Mm + tid]);
                s_kr[tid] = __ldcg(&g_k[Bb*Mm + b*Mm + tid]);
                s_e[tid]  = __ldcg(&g_e[b*Mm + tid]);
                s_a[tid]  = __ldcg(&g_a[b*Mm + tid]);
            }
            // 12 small projections for this batch, warp per channel
            for (int c = wid; c < 12; c += 8){
                int hd = c / 6, cc = c % 6;
                const float* wp; float bi; int stride;
                if      (cc == 0){ wp = Wb   + hd*Hh;            bi = bb[hd];            stride = 1; }
                else if (cc == 1){ wp = Wg   + hd*Hh;            bi = bg[hd];            stride = 1; }
                else if (cc == 2){ wp = Wgam + hd*Hh;            bi = bgam[hd];          stride = 1; }
                else             { wp = Ws   + hd*Hh*3 + (cc-3); bi = bs[hd*3 + cc-3];   stride = 3; }
                float acc = 0.f;
                for (int h = lane; h < Hh; h += 32)
                    acc += __ldcg(&g_ht[b*Hh + h]) * wp[h*stride];
                #pragma unroll
                for (int off = 16; off; off >>= 1) acc += __shfl_xor_sync(0xffffffffu, acc, off);
                if (lane == 0) s_sm[c] = acc + bi;
            }
            __syncthreads();
            // key norms
            {
                float v  = (tid < 128) ? s_kw[tid] : s_kr[tid - 128];
                float sq = v * v;
                #pragma unroll
                for (int off = 16; off; off >>= 1) sq += __shfl_xor_sync(0xffffffffu, sq, off);
                if (lane == 0) s_red[wid] = sq;
                __syncthreads();
                if (tid == 0){
                    s_red[32] = fmaxf(sqrtf(s_red[0]+s_red[1]+s_red[2]+s_red[3]), EPSf);
                    s_red[33] = fmaxf(sqrtf(s_red[4]+s_red[5]+s_red[6]+s_red[7]), EPSf);
                }
                __syncthreads();
            }
            const float ibw = softplusf(s_sm[0]) / s_red[32];
            const float ibr = softplusf(s_sm[6]) / s_red[33];
            __syncthreads();
            // cosine for both heads, one memory sweep, 2 rows/iter for ILP
            {
                const float4* m4  = ((const float4*)g_mem) + b * (Nn*Mm/4);
                const float4  kw4 = ((float4*)s_kw)[lane];
                const float4  kr4 = ((float4*)s_kr)[lane];
                for (int j = 0; j < 32; j += 2){
                    int n0 = wid*32 + j, n1 = n0 + 1;
                    float4 m0 = m4[n0*32 + lane];
                    float4 m1 = m4[n1*32 + lane];
                    float dw0 = m0.x*kw4.x + m0.y*kw4.y + m0.z*kw4.z + m0.w*kw4.w;
                    float dr0 = m0.x*kr4.x + m0.y*kr4.y + m0.z*kr4.z + m0.w*kr4.w;
                    float nn0 = m0.x*m0.x + m0.y*m0.y + m0.z*m0.z + m0.w*m0.w;
                    float dw1 = m1.x*kw4.x + m1.y*kw4.y + m1.z*kw4.z + m1.w*kw4.w;
                    float dr1 = m1.x*kr4.x + m1.y*kr4.y + m1.z*kr4.z + m1.w*kr4.w;
                    float nn1 = m1.x*m1.x + m1.y*m1.y + m1.z*m1.z + m1.w*m1.w;
                    #pragma unroll
                    for (int off = 16; off; off >>= 1){
                        dw0 += __shfl_xor_sync(0xffffffffu, dw0, off);
                        dw1 += __shfl_xor_sync(0xffffffffu, dw1, off);
                        dr0 += __shfl_xor_sync(0xffffffffu, dr0, off);
                        dr1 += __shfl_xor_sync(0xffffffffu, dr1, off);
                        nn0 += __shfl_xor_sync(0xffffffffu, nn0, off);
                        nn1 += __shfl_xor_sync(0xffffffffu, nn1, off);
                    }
                    if (lane == 0){
                        float i0 = 1.f / fmaxf(sqrtf(nn0), EPSf);
                        float i1 = 1.f / fmaxf(sqrtf(nn1), EPSf);
                        s_zw[n0] = dw0 * ibw * i0;  s_zw[n1] = dw1 * ibw * i1;
                        s_zr[n0] = dr0 * ibr * i0;  s_zr[n1] = dr1 * ibr * i1;
                    }
                }
                __syncthreads();
            }
            // per-head weight pipeline (n = tid)
            #pragma unroll 1
            for (int hd = 0; hd < 2; hd++){
                float* sz    = hd ? s_zr : s_zw;
                float* sprev = hd ? s_rw : s_ww;
                float graw = s_sm[hd*6 + 1];
                float gamr = s_sm[hd*6 + 2];
                float r0s  = s_sm[hd*6 + 3], r1s = s_sm[hd*6 + 4], r2s = s_sm[hd*6 + 5];
                float z  = sz[tid];
                float mx = bredMax(z, s_red);
                float ez = expf(z - mx);
                float sm = bredSum(ez, s_red);
                float wc = ez / sm;
                float g  = sigmoidf_(graw);
                s_tmp[tid] = g*wc + (1.f - g)*sprev[tid];
                __syncthreads();
                float m3 = fmaxf(r0s, fmaxf(r1s, r2s));
                float e0 = expf(r0s - m3), e1 = expf(r1s - m3), e2 = expf(r2s - m3);
                float i3 = 1.f / (e0 + e1 + e2);
                float wsh = e0*i3 * s_tmp[(tid + 255) & 255]
                          + e1*i3 * s_tmp[tid]
                          + e2*i3 * s_tmp[(tid + 1) & 255];
                float gamma = fmaxf(gamr, 0.f) + 1.f;
                float wpow  = powf(wsh, gamma);
                float tsum  = bredSum(wpow, s_red);
                sprev[tid]  = wpow / tsum;
            }
            __syncthreads();
        }

        // ===== P4 (CTA b): memory update + rd =====
        {
            const int mq    = tid & 31;
            const int rbase = tid >> 5;
            const float4 e4 = ((float4*)s_e)[mq];
            const float4 a4 = ((float4*)s_a)[mq];
            float4* m4 = ((float4*)g_mem) + b * (Nn*Mm/4);
            float4 prd = make_float4(0,0,0,0);
            #pragma unroll 4
            for (int it = 0; it < 32; it++){
                int n = it*8 + rbase;
                float wwn = s_ww[n], rwn = s_rw[n];
                float4 mv = m4[n*32 + mq];
                float4 nv;
                nv.x = mv.x*(1.f - wwn*e4.x) + wwn*a4.x;
                nv.y = mv.y*(1.f - wwn*e4.y) + wwn*a4.y;
                nv.z = mv.z*(1.f - wwn*e4.z) + wwn*a4.z;
                nv.w = mv.w*(1.f - wwn*e4.w) + wwn*a4.w;
                m4[n*32 + mq] = nv;
                prd.x += rwn*nv.x; prd.y += rwn*nv.y; prd.z += rwn*nv.z; prd.w += rwn*nv.w;
            }
            s_prd[tid] = prd;
            __syncthreads();
            if (tid < 32){
                float4 r = s_prd[tid];
                #pragma unroll
                for (int j = 1; j < 8; j++){
                    float4 v = s_prd[tid + 32*j];
                    r.x += v.x; r.y += v.y; r.z += v.z; r.w += v.w;
                }
                __stcg(((float4*)g_rd) + b*32 + tid, r);
            }
        }
    }

    // ===== tail: out[63] = rd_63 @ Wo + bo =====
    gbar();
    if (tid < 128){
        int r = tid >> 2, c = tid & 3;
        int row = RB1*32 + r, col = CB1*4 + c;
        float acc = 0.f;
        #pragma unroll 8
        for (int m = 0; m < 128; m++)
            acc += __ldcg(&g_rd[row*Mm + m]) * __ldg(&Wo[m*Ii + col]);
        out[63*(Bb*Ii) + row*Ii + col] = acc + bo[col];
    }
}

extern "C" void kernel_launch(void* const* d_in, const int* in_sizes, int n_in,
                              void* d_out, int out_size){
    (void)in_sizes; (void)n_in; (void)out_size;
    ntm_kernel<<<NCTA, NTHR>>>(
        (const float*)d_in[0],  (const float*)d_in[1],  (const float*)d_in[2],
        (const float*)d_in[3],  (const float*)d_in[4],  (const float*)d_in[5],
        (const float*)d_in[6],  (const float*)d_in[7],  (const float*)d_in[8],
        (const float*)d_in[9],  (const float*)d_in[10], (const float*)d_in[11],
        (const float*)d_in[12], (const float*)d_in[13], (const float*)d_in[14],
        (const float*)d_in[15], (const float*)d_in[16], (const float*)d_in[17],
        (const float*)d_in[18], (const float*)d_in[19], (const float*)d_in[20],
        (const float*)d_in[21], (const float*)d_in[22],
        (float*)d_out);
}